// round 3
// baseline (speedup 1.0000x reference)
#include <cuda_runtime.h>
#include <cstdint>
#include <cstddef>

#define BB 16
#define NN 4096
#define SS 1024
#define KK 32
#define NT (BB*SS*KK)          // 524288 sample columns
#define OUT_XYZ (BB*SS*3)      // 49152

typedef unsigned long long ull;

// ---------------- device scratch (no allocation allowed) ---------------------
__device__ float g_X0[(size_t)67*NT];   // conv1 input; reused as Y2 (64 planes)
__device__ float g_Y1[(size_t)64*NT];
__device__ float g_Y3[(size_t)128*NT];
__device__ int    g_gidx[BB*SS*KK];
__device__ float2 g_part[128*16];
__device__ float  g_sc1[64],  g_sh1[64];
__device__ float  g_sc2[64],  g_sh2[64];
__device__ float  g_sc3[128], g_sh3[128];

// ---------------- packed f32x2 helpers ---------------------------------------
__device__ __forceinline__ ull pk2(float a, float b){
    ull r; asm("mov.b64 %0, {%1,%2};" : "=l"(r) : "f"(a), "f"(b)); return r;
}
__device__ __forceinline__ void upk2(ull v, float& a, float& b){
    asm("mov.b64 {%0,%1}, %2;" : "=f"(a), "=f"(b) : "l"(v));
}
__device__ __forceinline__ ull add2(ull a, ull b){
    ull r; asm("add.rn.f32x2 %0, %1, %2;" : "=l"(r) : "l"(a), "l"(b)); return r;
}
__device__ __forceinline__ ull mul2(ull a, ull b){
    ull r; asm("mul.rn.f32x2 %0, %1, %2;" : "=l"(r) : "l"(a), "l"(b)); return r;
}
__device__ __forceinline__ ull fma2(ull a, ull b, ull c){
    ull r; asm("fma.rn.f32x2 %0, %1, %2, %3;" : "=l"(r) : "l"(a), "l"(b), "l"(c)); return r;
}

// ---------------- 1) farthest point sampling (1 CTA / batch) -----------------
#define FPS_T 512
__global__ void __launch_bounds__(FPS_T, 1)
fps_kernel(const float* __restrict__ xyz, float* __restrict__ out)
{
    __shared__ float swmax[FPS_T/32];
    __shared__ float s_maxv;
    __shared__ int   s_arg;

    const int b = blockIdx.x, t = threadIdx.x, lane = t & 31, wid = t >> 5;
    const float* base = xyz + (size_t)b*NN*3;
    const int j0 = t * 8;                       // 8 points per thread

    ull px[4], py[4], pz[4];
    float d[8];
#pragma unroll
    for (int k = 0; k < 4; k++){
        int j = j0 + 2*k;
        px[k] = pk2(base[3*j+0], base[3*j+3]);
        py[k] = pk2(base[3*j+1], base[3*j+4]);
        pz[k] = pk2(base[3*j+2], base[3*j+5]);
    }
#pragma unroll
    for (int k = 0; k < 8; k++) d[k] = 1e10f;

    int far = 0;
    float* ob = out + (size_t)b*SS*3;
    for (int it = 0; it < SS; ++it){
        const float cx = base[3*far], cy = base[3*far+1], cz = base[3*far+2];
        if (t == 0){ ob[3*it] = cx; ob[3*it+1] = cy; ob[3*it+2] = cz; }
        const ull ncx = pk2(-cx,-cx), ncy = pk2(-cy,-cy), ncz = pk2(-cz,-cz);

        float mx = -1.0f;
#pragma unroll
        for (int k = 0; k < 4; k++){
            ull dx = add2(px[k], ncx);
            ull dy = add2(py[k], ncy);
            ull dz = add2(pz[k], ncz);
            // ((dx*dx + dy*dy) + dz*dz), all RN, no fma — matches reference chain
            ull s  = add2(add2(mul2(dx,dx), mul2(dy,dy)), mul2(dz,dz));
            float lo, hi; upk2(s, lo, hi);
            d[2*k]   = fminf(d[2*k],   lo);
            d[2*k+1] = fminf(d[2*k+1], hi);
            mx = fmaxf(mx, fmaxf(d[2*k], d[2*k+1]));
        }
#pragma unroll
        for (int o = 16; o > 0; o >>= 1) mx = fmaxf(mx, __shfl_xor_sync(0xffffffffu, mx, o));
        if (lane == 0) swmax[wid] = mx;
        __syncthreads();
        if (t == 0){
            float v = swmax[0];
#pragma unroll
            for (int i = 1; i < FPS_T/32; i++) v = fmaxf(v, swmax[i]);
            s_maxv = v;
            s_arg  = 0x7fffffff;
        }
        __syncthreads();
        const float gmax = s_maxv;
        if (swmax[wid] == gmax){
#pragma unroll
            for (int k = 0; k < 8; k++)
                if (d[k] == gmax) atomicMin(&s_arg, j0 + k);   // first occurrence = min index
        }
        __syncthreads();
        far = s_arg;
    }
}

// ---------------- 2) ball query: first 32 in-ball by ascending index ---------
__global__ void __launch_bounds__(256)
query_kernel(const float* __restrict__ xyz, const float* __restrict__ newxyz,
             int* __restrict__ gidx)
{
    const int warp = threadIdx.x >> 5, lane = threadIdx.x & 31;
    const int g = blockIdx.x * 8 + warp;          // b*1024 + s
    const int b = g >> 10;
    const float* P = xyz + (size_t)b*NN*3;
    const float cx = newxyz[3*g], cy = newxyz[3*g+1], cz = newxyz[3*g+2];
    const float cn = __fadd_rn(__fadd_rn(__fmul_rn(cx,cx), __fmul_rn(cy,cy)), __fmul_rn(cz,cz));
    const float RR = (float)(0.2*0.2);

    int count = 0, first = -1;
    int* outp = gidx + (size_t)g*KK;
    for (int c0 = 0; c0 < NN; c0 += 32){
        const int j = c0 + lane;
        const float x = P[3*j], y = P[3*j+1], z = P[3*j+2];
        const float dot = __fadd_rn(__fadd_rn(__fmul_rn(x,cx), __fmul_rn(y,cy)), __fmul_rn(z,cz));
        const float pn  = __fadd_rn(__fadd_rn(__fmul_rn(x,x),  __fmul_rn(y,y)),  __fmul_rn(z,z));
        const float dd  = __fadd_rn(__fadd_rn(__fmul_rn(-2.0f, dot), cn), pn);
        const bool ok = !(dd > RR);
        const unsigned m = __ballot_sync(0xffffffffu, ok);
        if (m){
            if (first < 0) first = c0 + __ffs(m) - 1;
            const int pos = count + __popc(m & ((1u << lane) - 1u));
            if (ok && pos < KK) outp[pos] = j;
            count += __popc(m);
            if (count >= KK) break;
        }
    }
    __syncwarp();
    if (count < KK){
        const int f = (first >= 0) ? first : 0;   // centroid itself is always in-ball
        for (int p = count + lane; p < KK; p += 32) outp[p] = f;
    }
}

// ---------------- 3) gather: build X0 [67][NT] channel-major -----------------
__global__ void __launch_bounds__(256)
gather_kernel(const float* __restrict__ xyz, const float* __restrict__ points,
              const float* __restrict__ newxyz, const int* __restrict__ gidx,
              float* __restrict__ X0)
{
    const int warp = threadIdx.x >> 5, lane = threadIdx.x & 31;
    const int g = blockIdx.x * 8 + warp;
    const int b = g >> 10;
    const int idx = gidx[(size_t)g*KK + lane];
    const size_t n = (size_t)g*KK + lane;

    const float* P = xyz + ((size_t)b*NN + idx)*3;
    const float cx = newxyz[3*g], cy = newxyz[3*g+1], cz = newxyz[3*g+2];
    X0[(size_t)0*NT + n] = __fsub_rn(P[0], cx);
    X0[(size_t)1*NT + n] = __fsub_rn(P[1], cy);
    X0[(size_t)2*NT + n] = __fsub_rn(P[2], cz);

    const float4* F = (const float4*)(points + ((size_t)b*NN + idx)*64);
#pragma unroll
    for (int c4 = 0; c4 < 16; c4++){
        const float4 v = F[c4];
        X0[(size_t)(3+4*c4+0)*NT + n] = v.x;
        X0[(size_t)(3+4*c4+1)*NT + n] = v.y;
        X0[(size_t)(3+4*c4+2)*NT + n] = v.z;
        X0[(size_t)(3+4*c4+3)*NT + n] = v.w;
    }
}

// ---------------- 4) conv (1x1) GEMM: Y[o][n] = sum_c W[o][c]*X[c][n] + b ----
// Tile: 128 columns x all O rows. 256 threads: tx = 32 column lanes (4 cols
// each, paired as f32x2), ty = 8 row groups of O/8 rows. Input-side BN+ReLU
// fused when NORM (applies previous layer's affine before multiply).
template<int C, int O, bool NORM>
__global__ void __launch_bounds__(256)
conv_kernel(const float* __restrict__ X, const float* __restrict__ W,
            const float* __restrict__ bias, const float* __restrict__ sc,
            const float* __restrict__ sh, float* __restrict__ Y)
{
    extern __shared__ float smem[];
    float* Ws = smem;            // O*C
    float* Xs = smem + O*C;      // C*128

    const int nb = blockIdx.x * 128;
    const int t  = threadIdx.x, tx = t & 31, ty = t >> 5;
    constexpr int RPT = O / 8;

    for (int i = t; i < O*C; i += 256) Ws[i] = W[i];
    for (int i = t; i < C*128; i += 256){
        const int c = i >> 7, col = i & 127;
        float v = X[(size_t)c*NT + nb + col];
        if (NORM) v = fmaxf(__fmaf_rn(v, sc[c], sh[c]), 0.0f);
        Xs[i] = v;
    }
    __syncthreads();

    ull acc[RPT][2];
#pragma unroll
    for (int r = 0; r < RPT; r++){ acc[r][0] = 0ull; acc[r][1] = 0ull; }

#pragma unroll 4
    for (int c = 0; c < C; c++){
        const float* xr = Xs + c*128 + tx;
        const ull a01 = pk2(xr[0],  xr[32]);
        const ull a23 = pk2(xr[64], xr[96]);
#pragma unroll
        for (int r = 0; r < RPT; r++){
            const float w = Ws[(ty*RPT + r)*C + c];
            const ull wp = pk2(w, w);
            acc[r][0] = fma2(wp, a01, acc[r][0]);
            acc[r][1] = fma2(wp, a23, acc[r][1]);
        }
    }

#pragma unroll
    for (int r = 0; r < RPT; r++){
        const int o = ty*RPT + r;
        const float bo = bias[o];
        float v0,v1,v2,v3;
        upk2(acc[r][0], v0, v1); upk2(acc[r][1], v2, v3);
        float* yr = Y + (size_t)o*NT + nb + tx;
        yr[0]  = __fadd_rn(v0, bo);
        yr[32] = __fadd_rn(v1, bo);
        yr[64] = __fadd_rn(v2, bo);
        yr[96] = __fadd_rn(v3, bo);
    }
}

// ---------------- 5) BN stats: partial sums per (channel, chunk) -------------
__global__ void __launch_bounds__(256)
stats_kernel(const float* __restrict__ Y, float2* __restrict__ part)
{
    const int o = blockIdx.x;
    const size_t base = (size_t)o*NT + (size_t)blockIdx.y*32768;
    float s = 0.f, q = 0.f;
    for (int i = threadIdx.x; i < 32768; i += 256){
        const float v = Y[base + i];
        s = __fadd_rn(s, v);
        q = __fmaf_rn(v, v, q);
    }
    __shared__ float2 red[8];
    const int lane = threadIdx.x & 31, wid = threadIdx.x >> 5;
#pragma unroll
    for (int off = 16; off > 0; off >>= 1){
        s += __shfl_xor_sync(0xffffffffu, s, off);
        q += __shfl_xor_sync(0xffffffffu, q, off);
    }
    if (lane == 0) red[wid] = make_float2(s, q);
    __syncthreads();
    if (threadIdx.x == 0){
        float ts = 0.f, tq = 0.f;
#pragma unroll
        for (int i = 0; i < 8; i++){ ts += red[i].x; tq += red[i].y; }
        part[o*16 + blockIdx.y] = make_float2(ts, tq);
    }
}

__global__ void finalize_kernel(const float2* __restrict__ part,
                                const float* __restrict__ gam,
                                const float* __restrict__ beta,
                                float* __restrict__ sc, float* __restrict__ sh)
{
    const int o = threadIdx.x;
    float s = 0.f, q = 0.f;
    for (int i = 0; i < 16; i++){ const float2 p = part[o*16+i]; s += p.x; q += p.y; }
    const float inv_n = 1.0f / (float)NT;
    const float mean = s * inv_n;
    const float var  = q * inv_n - mean * mean;
    const float inv  = rsqrtf(var + 1e-5f);
    const float scale = inv * gam[o];
    sc[o] = scale;
    sh[o] = beta[o] - mean * scale;
}

// ---------------- 6) max-pool over the 32 samples + final BN+ReLU ------------
__global__ void __launch_bounds__(256)
pool_kernel(const float* __restrict__ Y3, const float* __restrict__ sc,
            const float* __restrict__ sh, float* __restrict__ out)
{
    const int o = blockIdx.y;
    const int g = blockIdx.x * 256 + threadIdx.x;
    const float scale = sc[o], shift = sh[o];
    const float4* p = (const float4*)(Y3 + (size_t)o*NT + (size_t)g*32);
    float m = 0.0f;                               // ReLU floor
#pragma unroll
    for (int i = 0; i < 8; i++){
        const float4 v = p[i];
        m = fmaxf(m, fmaxf(__fmaf_rn(v.x, scale, shift), __fmaf_rn(v.y, scale, shift)));
        m = fmaxf(m, fmaxf(__fmaf_rn(v.z, scale, shift), __fmaf_rn(v.w, scale, shift)));
    }
    out[OUT_XYZ + (size_t)g*128 + o] = m;
}

// ---------------- launch ------------------------------------------------------
extern "C" void kernel_launch(void* const* d_in, const int* in_sizes, int n_in,
                              void* d_out, int out_size)
{
    const float* xyz    = (const float*)d_in[0];
    const float* points = (const float*)d_in[1];
    const float* w1 = (const float*)d_in[2];
    const float* b1 = (const float*)d_in[3];
    const float* g1 = (const float*)d_in[4];
    const float* be1= (const float*)d_in[5];
    const float* w2 = (const float*)d_in[6];
    const float* b2 = (const float*)d_in[7];
    const float* g2 = (const float*)d_in[8];
    const float* be2= (const float*)d_in[9];
    const float* w3 = (const float*)d_in[10];
    const float* b3 = (const float*)d_in[11];
    const float* g3 = (const float*)d_in[12];
    const float* be3= (const float*)d_in[13];
    float* out = (float*)d_out;

    float *X0, *Y1, *Y3; int* gidx; float2* part;
    float *sc1,*sh1,*sc2,*sh2,*sc3,*sh3;
    cudaGetSymbolAddress((void**)&X0,  g_X0);
    cudaGetSymbolAddress((void**)&Y1,  g_Y1);
    cudaGetSymbolAddress((void**)&Y3,  g_Y3);
    cudaGetSymbolAddress((void**)&gidx,g_gidx);
    cudaGetSymbolAddress((void**)&part,g_part);
    cudaGetSymbolAddress((void**)&sc1, g_sc1);
    cudaGetSymbolAddress((void**)&sh1, g_sh1);
    cudaGetSymbolAddress((void**)&sc2, g_sc2);
    cudaGetSymbolAddress((void**)&sh2, g_sh2);
    cudaGetSymbolAddress((void**)&sc3, g_sc3);
    cudaGetSymbolAddress((void**)&sh3, g_sh3);

    const int S1 = (64*67 + 67*128) * 4;   // 51456 B
    const int S2 = (64*64 + 64*128) * 4;   // 49152 B
    const int S3 = (128*64 + 64*128) * 4;  // 65536 B
    cudaFuncSetAttribute(conv_kernel<67,64,false>, cudaFuncAttributeMaxDynamicSharedMemorySize, S1);
    cudaFuncSetAttribute(conv_kernel<64,64,true>,  cudaFuncAttributeMaxDynamicSharedMemorySize, S2);
    cudaFuncSetAttribute(conv_kernel<64,128,true>, cudaFuncAttributeMaxDynamicSharedMemorySize, S3);

    // 1) FPS -> new_xyz (first OUT_XYZ floats of out)
    fps_kernel<<<BB, FPS_T>>>(xyz, out);
    // 2) ball query
    query_kernel<<<BB*SS/8, 256>>>(xyz, out, gidx);
    // 3) gather/group -> X0 [67][NT]
    gather_kernel<<<BB*SS/8, 256>>>(xyz, points, out, gidx, X0);
    // 4) conv1 -> Y1, stats
    conv_kernel<67,64,false><<<NT/128, 256, S1>>>(X0, w1, b1, nullptr, nullptr, Y1);
    stats_kernel<<<dim3(64,16), 256>>>(Y1, part);
    finalize_kernel<<<1, 64>>>(part, g1, be1, sc1, sh1);
    // 5) conv2 (reads Y1 with fused BN+ReLU) -> Y2 (reuse X0 planes)
    conv_kernel<64,64,true><<<NT/128, 256, S2>>>(Y1, w2, b2, sc1, sh1, X0);
    stats_kernel<<<dim3(64,16), 256>>>(X0, part);
    finalize_kernel<<<1, 64>>>(part, g2, be2, sc2, sh2);
    // 6) conv3 -> Y3
    conv_kernel<64,128,true><<<NT/128, 256, S3>>>(X0, w3, b3, sc2, sh2, Y3);
    stats_kernel<<<dim3(128,16), 256>>>(Y3, part);
    finalize_kernel<<<1, 128>>>(part, g3, be3, sc3, sh3);
    // 7) pool + final BN+ReLU -> new_points
    pool_kernel<<<dim3(BB*SS/256, 128), 256>>>(Y3, sc3, sh3, out);
}

// round 16
// speedup vs baseline: 1.1872x; 1.1872x over previous
#include <cuda_runtime.h>
#include <cstdint>
#include <cstddef>

#define BB 16
#define NN 4096
#define SS 1024
#define KK 32
#define NT (BB*SS*KK)          // 524288 sample columns
#define OUT_XYZ (BB*SS*3)      // 49152

typedef unsigned long long ull;

// ---------------- device scratch (no allocation allowed) ---------------------
__device__ float  g_Y1[(size_t)64*NT];
__device__ float  g_Y2[(size_t)64*NT];
__device__ float  g_Y3[(size_t)128*NT];
__device__ int    g_gidx[BB*SS*KK];
__device__ float2 g_part[(size_t)128*4096];
__device__ float  g_sc1[64],  g_sh1[64];
__device__ float  g_sc2[64],  g_sh2[64];
__device__ float  g_sc3[128], g_sh3[128];

// ---------------- packed f32x2 helpers ---------------------------------------
__device__ __forceinline__ ull pk2(float a, float b){
    ull r; asm("mov.b64 %0, {%1,%2};" : "=l"(r) : "f"(a), "f"(b)); return r;
}
__device__ __forceinline__ void upk2(ull v, float& a, float& b){
    asm("mov.b64 {%0,%1}, %2;" : "=f"(a), "=f"(b) : "l"(v));
}
__device__ __forceinline__ ull add2(ull a, ull b){
    ull r; asm("add.rn.f32x2 %0, %1, %2;" : "=l"(r) : "l"(a), "l"(b)); return r;
}
__device__ __forceinline__ ull mul2(ull a, ull b){
    ull r; asm("mul.rn.f32x2 %0, %1, %2;" : "=l"(r) : "l"(a), "l"(b)); return r;
}
__device__ __forceinline__ ull fma2(ull a, ull b, ull c){
    ull r; asm("fma.rn.f32x2 %0, %1, %2, %3;" : "=l"(r) : "l"(a), "l"(b), "l"(c)); return r;
}

// ---------------- 1) farthest point sampling (1 CTA / batch) -----------------
// Distances are nonnegative floats, so u32 compare of their bits == float
// compare: __reduce_max_sync on bits is exact. Argmax tie-break = first index;
// lane/warp index ranges ascend with index, so first-match = reference argmax.
#define FPS_T 512
__global__ void __launch_bounds__(FPS_T, 1)
fps_kernel(const float* __restrict__ xyz, float* __restrict__ out)
{
    __shared__ unsigned swmax[16];
    __shared__ int      swidx[16];
    __shared__ int      s_far;

    const int b = blockIdx.x, t = threadIdx.x, lane = t & 31, wid = t >> 5;
    const float* base = xyz + (size_t)b*NN*3;
    const int j0 = t * 8;                       // 8 points per thread

    ull px[4], py[4], pz[4];
    float d[8];
#pragma unroll
    for (int k = 0; k < 4; k++){
        int j = j0 + 2*k;
        px[k] = pk2(base[3*j+0], base[3*j+3]);
        py[k] = pk2(base[3*j+1], base[3*j+4]);
        pz[k] = pk2(base[3*j+2], base[3*j+5]);
    }
#pragma unroll
    for (int k = 0; k < 8; k++) d[k] = 1e10f;

    int far = 0;
    float* ob = out + (size_t)b*SS*3;
    for (int it = 0; it < SS; ++it){
        const float cx = base[3*far], cy = base[3*far+1], cz = base[3*far+2];
        if (t == 0){ ob[3*it] = cx; ob[3*it+1] = cy; ob[3*it+2] = cz; }
        const ull ncx = pk2(-cx,-cx), ncy = pk2(-cy,-cy), ncz = pk2(-cz,-cz);

        float mx = -1.0f;
#pragma unroll
        for (int k = 0; k < 4; k++){
            ull dx = add2(px[k], ncx);
            ull dy = add2(py[k], ncy);
            ull dz = add2(pz[k], ncz);
            // ((dx*dx + dy*dy) + dz*dz), all RN, no fma — matches reference chain
            ull s  = add2(add2(mul2(dx,dx), mul2(dy,dy)), mul2(dz,dz));
            float lo, hi; upk2(s, lo, hi);
            d[2*k]   = fminf(d[2*k],   lo);
            d[2*k+1] = fminf(d[2*k+1], hi);
            mx = fmaxf(mx, fmaxf(d[2*k], d[2*k+1]));
        }
        // warp max + first-index argmax (exact)
        const unsigned mxb  = __float_as_uint(mx);          // mx >= 0 here
        const unsigned wmax = __reduce_max_sync(0xffffffffu, mxb);
        const unsigned ball = __ballot_sync(0xffffffffu, mxb == wmax);
        int firstk = 0;
#pragma unroll
        for (int k = 7; k >= 0; --k) if (__float_as_uint(d[k]) == wmax) firstk = k;
        const int cand = j0 + firstk;
        const int warg = __shfl_sync(0xffffffffu, cand, __ffs(ball) - 1);
        if (lane == 0){ swmax[wid] = wmax; swidx[wid] = warg; }
        __syncthreads();
        if (wid == 0){
            const unsigned v  = (lane < 16) ? swmax[lane] : 0u;
            const unsigned g  = __reduce_max_sync(0xffffffffu, v);
            const unsigned b2 = __ballot_sync(0xffffffffu, v == g) & 0xFFFFu;
            if (lane == 0) s_far = swidx[__ffs(b2) - 1];
        }
        __syncthreads();
        far = s_far;
    }
}

// ---------------- 2) ball query: first 32 in-ball by ascending index ---------
__global__ void __launch_bounds__(256)
query_kernel(const float* __restrict__ xyz, const float* __restrict__ newxyz,
             int* __restrict__ gidx)
{
    const int warp = threadIdx.x >> 5, lane = threadIdx.x & 31;
    const int g = blockIdx.x * 8 + warp;          // b*1024 + s
    const int b = g >> 10;
    const float* P = xyz + (size_t)b*NN*3;
    const float cx = newxyz[3*g], cy = newxyz[3*g+1], cz = newxyz[3*g+2];
    const float cn = __fadd_rn(__fadd_rn(__fmul_rn(cx,cx), __fmul_rn(cy,cy)), __fmul_rn(cz,cz));
    const float RR = (float)(0.2*0.2);

    int count = 0, first = -1;
    int* outp = gidx + (size_t)g*KK;
    for (int c0 = 0; c0 < NN; c0 += 32){
        const int j = c0 + lane;
        const float x = P[3*j], y = P[3*j+1], z = P[3*j+2];
        const float dot = __fadd_rn(__fadd_rn(__fmul_rn(x,cx), __fmul_rn(y,cy)), __fmul_rn(z,cz));
        const float pn  = __fadd_rn(__fadd_rn(__fmul_rn(x,x),  __fmul_rn(y,y)),  __fmul_rn(z,z));
        const float dd  = __fadd_rn(__fadd_rn(__fmul_rn(-2.0f, dot), cn), pn);
        const bool ok = !(dd > RR);
        const unsigned m = __ballot_sync(0xffffffffu, ok);
        if (m){
            if (first < 0) first = c0 + __ffs(m) - 1;
            const int pos = count + __popc(m & ((1u << lane) - 1u));
            if (ok && pos < KK) outp[pos] = j;
            count += __popc(m);
            if (count >= KK) break;
        }
    }
    __syncwarp();
    if (count < KK){
        const int f = (first >= 0) ? first : 0;   // centroid itself is always in-ball
        for (int p = count + lane; p < KK; p += 32) outp[p] = f;
    }
}

// ---------------- 3) conv (1x1) GEMM with fused input-norm / gather / stats --
// Block: 128 columns x 64 output rows (rowBase = blockIdx.y*64).
// 256 threads: tx = 32 lanes owning adjacent column pairs (2tx,2tx+1) and
// (64+2tx, 64+2tx+1); ty = 8 groups of 8 rows. W pre-duplicated as (w,w) u64
// in smem so the inner loop is pure LDS.64 + FFMA2.
// Epilogue adds bias, stores float2, and emits per-channel partial (sum,sumsq)
// for the following BN — deterministic fixed-tree reduction.
template<int C, bool NORM, bool GATHER>
__global__ void __launch_bounds__(256)
conv_kernel(const float* __restrict__ X, const float* __restrict__ W,
            const float* __restrict__ bias, const float* __restrict__ sc,
            const float* __restrict__ sh,
            const float* __restrict__ xyz, const float* __restrict__ points,
            const float* __restrict__ newxyz, const int* __restrict__ gidx,
            float* __restrict__ Y, float2* __restrict__ part)
{
    extern __shared__ char smem_raw[];
    ull*   Ws2 = (ull*)smem_raw;                      // 64*C duplicated weights
    float* Xs  = (float*)(smem_raw + (size_t)64*C*8); // C*128 input tile

    const int nb      = blockIdx.x * 128;
    const int rowBase = blockIdx.y * 64;
    const int t = threadIdx.x, tx = t & 31, ty = t >> 5;

    for (int i = t; i < 64*C; i += 256){
        const float w = W[(size_t)rowBase*C + i];
        Ws2[i] = pk2(w, w);
    }

    if (GATHER){
        // conv1: gather grouped features straight from xyz/points
        const int col = t & 127, half = t >> 7;
        const int n = nb + col, g = n >> 5, b = g >> 10;
        const int idx = gidx[n];
        const size_t prow = (size_t)b*NN + idx;
        if (half == 0){
            const float* Q = xyz + prow*3;
            Xs[0*128+col] = __fsub_rn(Q[0], newxyz[3*g]);
            Xs[1*128+col] = __fsub_rn(Q[1], newxyz[3*g+1]);
            Xs[2*128+col] = __fsub_rn(Q[2], newxyz[3*g+2]);
        }
        const float4* F = (const float4*)(points + prow*64 + half*32);
        const int cb = 3 + half*32;
#pragma unroll
        for (int j = 0; j < 8; j++){
            const float4 v = F[j];
            Xs[(cb+4*j+0)*128+col] = v.x;
            Xs[(cb+4*j+1)*128+col] = v.y;
            Xs[(cb+4*j+2)*128+col] = v.z;
            Xs[(cb+4*j+3)*128+col] = v.w;
        }
    } else {
        for (int i = t; i < C*128; i += 256){
            const int c = i >> 7, col = i & 127;
            float v = X[(size_t)c*NT + nb + col];
            if (NORM) v = fmaxf(__fmaf_rn(v, sc[c], sh[c]), 0.0f);
            Xs[i] = v;
        }
    }
    __syncthreads();

    ull acc[8][2];
#pragma unroll
    for (int r = 0; r < 8; r++){ acc[r][0] = 0ull; acc[r][1] = 0ull; }

    const ull* wr = Ws2 + ty*8*C;
#pragma unroll 2
    for (int c = 0; c < C; c++){
        const ull a0 = *(const ull*)(Xs + c*128 + 2*tx);
        const ull a1 = *(const ull*)(Xs + c*128 + 64 + 2*tx);
#pragma unroll
        for (int r = 0; r < 8; r++){
            const ull w = wr[r*C + c];
            acc[r][0] = fma2(w, a0, acc[r][0]);
            acc[r][1] = fma2(w, a1, acc[r][1]);
        }
    }

    const int gb = gridDim.x;
#pragma unroll
    for (int r = 0; r < 8; r++){
        const int o = rowBase + ty*8 + r;
        const float bo = bias[o];
        float v0,v1,v2,v3;
        upk2(acc[r][0], v0, v1); upk2(acc[r][1], v2, v3);
        v0 = __fadd_rn(v0, bo); v1 = __fadd_rn(v1, bo);
        v2 = __fadd_rn(v2, bo); v3 = __fadd_rn(v3, bo);
        float* yr = Y + (size_t)o*NT + nb;
        *(float2*)(yr + 2*tx)      = make_float2(v0, v1);
        *(float2*)(yr + 64 + 2*tx) = make_float2(v2, v3);
        // per-channel partial stats over this block's 128 columns
        float s = __fadd_rn(__fadd_rn(v0, v1), __fadd_rn(v2, v3));
        float q = __fmaf_rn(v0, v0, __fmaf_rn(v1, v1, __fmaf_rn(v2, v2, __fmul_rn(v3, v3))));
#pragma unroll
        for (int off = 16; off > 0; off >>= 1){
            s = __fadd_rn(s, __shfl_xor_sync(0xffffffffu, s, off));
            q = __fadd_rn(q, __shfl_xor_sync(0xffffffffu, q, off));
        }
        if (tx == 0) part[(size_t)o*gb + blockIdx.x] = make_float2(s, q);
    }
}

// ---------------- 4) finalize BN: reduce partials -> scale/shift -------------
__global__ void __launch_bounds__(256)
finalize_kernel(const float2* __restrict__ part, const float* __restrict__ gam,
                const float* __restrict__ beta, float* __restrict__ sc,
                float* __restrict__ sh)
{
    const int o = blockIdx.x;
    const float2* p = part + (size_t)o*4096;
    float s = 0.f, q = 0.f;
    for (int i = threadIdx.x; i < 4096; i += 256){
        const float2 v = p[i];
        s = __fadd_rn(s, v.x); q = __fadd_rn(q, v.y);
    }
    __shared__ float2 red[8];
    const int lane = threadIdx.x & 31, wid = threadIdx.x >> 5;
#pragma unroll
    for (int off = 16; off > 0; off >>= 1){
        s = __fadd_rn(s, __shfl_xor_sync(0xffffffffu, s, off));
        q = __fadd_rn(q, __shfl_xor_sync(0xffffffffu, q, off));
    }
    if (lane == 0) red[wid] = make_float2(s, q);
    __syncthreads();
    if (threadIdx.x == 0){
        float ts = 0.f, tq = 0.f;
#pragma unroll
        for (int i = 0; i < 8; i++){ ts = __fadd_rn(ts, red[i].x); tq = __fadd_rn(tq, red[i].y); }
        const float inv_n = 1.0f / (float)NT;
        const float mean = ts * inv_n;
        const float var  = tq * inv_n - mean * mean;
        const float inv  = rsqrtf(var + 1e-5f);
        const float scale = inv * gam[o];
        sc[o] = scale;
        sh[o] = beta[o] - mean * scale;
    }
}

// ---------------- 5) max-pool over the 32 samples + final BN+ReLU ------------
__global__ void __launch_bounds__(256)
pool_kernel(const float* __restrict__ Y3, const float* __restrict__ sc,
            const float* __restrict__ sh, float* __restrict__ out)
{
    const int o = blockIdx.y;
    const int g = blockIdx.x * 256 + threadIdx.x;
    const float scale = sc[o], shift = sh[o];
    const float4* p = (const float4*)(Y3 + (size_t)o*NT + (size_t)g*32);
    float m = 0.0f;                               // ReLU floor
#pragma unroll
    for (int i = 0; i < 8; i++){
        const float4 v = p[i];
        m = fmaxf(m, fmaxf(__fmaf_rn(v.x, scale, shift), __fmaf_rn(v.y, scale, shift)));
        m = fmaxf(m, fmaxf(__fmaf_rn(v.z, scale, shift), __fmaf_rn(v.w, scale, shift)));
    }
    out[OUT_XYZ + (size_t)g*128 + o] = m;
}

// ---------------- launch ------------------------------------------------------
extern "C" void kernel_launch(void* const* d_in, const int* in_sizes, int n_in,
                              void* d_out, int out_size)
{
    const float* xyz    = (const float*)d_in[0];
    const float* points = (const float*)d_in[1];
    const float* w1 = (const float*)d_in[2];
    const float* b1 = (const float*)d_in[3];
    const float* g1 = (const float*)d_in[4];
    const float* be1= (const float*)d_in[5];
    const float* w2 = (const float*)d_in[6];
    const float* b2 = (const float*)d_in[7];
    const float* g2 = (const float*)d_in[8];
    const float* be2= (const float*)d_in[9];
    const float* w3 = (const float*)d_in[10];
    const float* b3 = (const float*)d_in[11];
    const float* g3 = (const float*)d_in[12];
    const float* be3= (const float*)d_in[13];
    float* out = (float*)d_out;

    float *Y1, *Y2, *Y3; int* gidx; float2* part;
    float *sc1,*sh1,*sc2,*sh2,*sc3,*sh3;
    cudaGetSymbolAddress((void**)&Y1,  g_Y1);
    cudaGetSymbolAddress((void**)&Y2,  g_Y2);
    cudaGetSymbolAddress((void**)&Y3,  g_Y3);
    cudaGetSymbolAddress((void**)&gidx,g_gidx);
    cudaGetSymbolAddress((void**)&part,g_part);
    cudaGetSymbolAddress((void**)&sc1, g_sc1);
    cudaGetSymbolAddress((void**)&sh1, g_sh1);
    cudaGetSymbolAddress((void**)&sc2, g_sc2);
    cudaGetSymbolAddress((void**)&sh2, g_sh2);
    cudaGetSymbolAddress((void**)&sc3, g_sc3);
    cudaGetSymbolAddress((void**)&sh3, g_sh3);

    const int S1 = 64*67*8 + 67*128*4;   // 68608 B
    const int S2 = 64*64*8 + 64*128*4;   // 65536 B
    cudaFuncSetAttribute(conv_kernel<67,false,true>, cudaFuncAttributeMaxDynamicSharedMemorySize, S1);
    cudaFuncSetAttribute(conv_kernel<64,true,false>, cudaFuncAttributeMaxDynamicSharedMemorySize, S2);

    // 1) FPS -> new_xyz (first OUT_XYZ floats of out)
    fps_kernel<<<BB, FPS_T>>>(xyz, out);
    // 2) ball query
    query_kernel<<<BB*SS/8, 256>>>(xyz, out, gidx);
    // 3) conv1 with fused gather + stats -> Y1
    conv_kernel<67,false,true><<<dim3(4096,1), 256, S1>>>(
        nullptr, w1, b1, nullptr, nullptr, xyz, points, out, gidx, Y1, part);
    finalize_kernel<<<64, 256>>>(part, g1, be1, sc1, sh1);
    // 4) conv2 (fused BN+ReLU on input) -> Y2
    conv_kernel<64,true,false><<<dim3(4096,1), 256, S2>>>(
        Y1, w2, b2, sc1, sh1, nullptr, nullptr, nullptr, nullptr, Y2, part);
    finalize_kernel<<<64, 256>>>(part, g2, be2, sc2, sh2);
    // 5) conv3 (rows split over grid.y) -> Y3
    conv_kernel<64,true,false><<<dim3(4096,2), 256, S2>>>(
        Y2, w3, b3, sc2, sh2, nullptr, nullptr, nullptr, nullptr, Y3, part);
    finalize_kernel<<<128, 256>>>(part, g3, be3, sc3, sh3);
    // 6) pool + final BN+ReLU -> new_points
    pool_kernel<<<dim3(BB*SS/256, 128), 256>>>(Y3, sc3, sh3, out);
}